// round 11
// baseline (speedup 1.0000x reference)
#include <cuda_runtime.h>
#include <cstdint>

// Problem constants
#define BATCH 32
#define NPTS  8192
#define DIM   128
#define LAM   0.01f

// split-K SYRK config
#define SPLITS 8
#define KC     (NPTS / SPLITS)   // 1024 k-rows per CTA
#define KT     32                // k-rows per smem tile
#define TILES  (KC / KT)         // 32
#define SD     136               // smem row stride (floats)

// Static device scratch
__device__ float g_covp[SPLITS][BATCH][DIM][DIM];  // partials (upper-right quadrant unused)
__device__ float g_sums[SPLITS][BATCH][DIM];
__device__ float g_keyp[SPLITS][BATCH][DIM];       // exact fp32 dot(col_d, col_0)
__device__ float g_cov[BATCH][DIM][DIM];

// ---------------------------------------------------------------------------
// tf32 warp MMA m16n8k8 — fragment layout VERIFIED (R7/R10 pass)
// ---------------------------------------------------------------------------
__device__ __forceinline__ void mma_tf32(float c[4],
                                         uint32_t a0, uint32_t a1, uint32_t a2, uint32_t a3,
                                         uint32_t b0, uint32_t b1) {
    asm volatile(
        "mma.sync.aligned.m16n8k8.row.col.f32.tf32.tf32.f32 "
        "{%0,%1,%2,%3}, {%4,%5,%6,%7}, {%8,%9}, {%0,%1,%2,%3};"
        : "+f"(c[0]), "+f"(c[1]), "+f"(c[2]), "+f"(c[3])
        : "r"(a0), "r"(a1), "r"(a2), "r"(a3), "r"(b0), "r"(b1));
}

__device__ __forceinline__ uint32_t to_tf32(float v) {
    uint32_t u;
    asm("cvt.rn.tf32.f32 %0, %1;" : "=r"(u) : "f"(v));
    return u;
}

// ---------------------------------------------------------------------------
// Kernel 1: symmetric split-K SYRK via tf32 mma.sync.
// Computes only blocks (0:128, 0:64) and (64:128, 64:128) — 12 strips of
// 16x64 — 3 strips per warp (24 MMA/ks each, SMSP-balanced).
// grid = BATCH*SPLITS, 128 threads (4 warps), 2 CTAs/SM.
// ---------------------------------------------------------------------------
__global__ __launch_bounds__(128, 2)
void syrk_mma_kernel(const float* __restrict__ x) {
    __shared__ float  sA[2][KT * SD];   // 2 x 17408 B
    __shared__ float4 sCsum[128];
    __shared__ float4 sKsum[128];

    const int bid = blockIdx.x;
    const int b = bid / SPLITS;
    const int s = bid % SPLITS;
    const float* __restrict__ xb = x + ((size_t)b * NPTS + (size_t)s * KC) * DIM;

    const int tid  = threadIdx.x;
    const int lane = tid & 31;
    const int wid  = tid >> 5;           // 0..3
    const int g    = lane >> 2;          // 0..7
    const int t4   = lane & 3;           // 0..3
    const int d4   = tid & 31;           // fixed column group (4 cols)
    const int krow = tid >> 5;           // 0..3 base k-row

    // strip assignment: rows of the 3 strips + which B set (cols 0:64 vs 64:128)
    int tm[3];
    bool b64_01, b64_2;                  // tiles {0,1} / tile {2} use B64?
    if (wid == 0)      { tm[0] = 0;  tm[1] = 16;  tm[2] = 32;  b64_01 = false; b64_2 = false; }
    else if (wid == 1) { tm[0] = 48; tm[1] = 64;  tm[2] = 80;  b64_01 = false; b64_2 = false; }
    else if (wid == 2) { tm[0] = 96; tm[1] = 112; tm[2] = 64;  b64_01 = false; b64_2 = true;  }
    else               { tm[0] = 80; tm[1] = 96;  tm[2] = 112; b64_01 = true;  b64_2 = true;  }

    float4 csum = make_float4(0.f, 0.f, 0.f, 0.f);
    float4 ksum = make_float4(0.f, 0.f, 0.f, 0.f);
    float acc[3][8][4];
#pragma unroll
    for (int j = 0; j < 3; ++j)
#pragma unroll
        for (int nt = 0; nt < 8; ++nt)
#pragma unroll
            for (int q = 0; q < 4; ++q) acc[j][nt][q] = 0.f;

    float4 pv[8];   // 8 rows x 4 cols per thread per tile

    // ---- prologue: load tile 0, accumulate, convert, store ----
    {
        const float4* src = (const float4*)xb;
#pragma unroll
        for (int r = 0; r < 8; ++r) pv[r] = __ldg(src + tid + 128 * r);
#pragma unroll
        for (int r = 0; r < 8; ++r) {
            const float x0 = __shfl_sync(0xffffffffu, pv[r].x, 0);
            csum.x += pv[r].x; csum.y += pv[r].y;
            csum.z += pv[r].z; csum.w += pv[r].w;
            ksum.x = fmaf(pv[r].x, x0, ksum.x);
            ksum.y = fmaf(pv[r].y, x0, ksum.y);
            ksum.z = fmaf(pv[r].z, x0, ksum.z);
            ksum.w = fmaf(pv[r].w, x0, ksum.w);
            const int k = krow + 4 * r;
            uint4 uv = make_uint4(to_tf32(pv[r].x), to_tf32(pv[r].y),
                                  to_tf32(pv[r].z), to_tf32(pv[r].w));
            *(uint4*)&sA[0][k * SD + d4 * 4] = uv;
        }
    }
    __syncthreads();

    // ---- main loop ----
    for (int t = 0; t < TILES; ++t) {
        const int cur = t & 1;

        if (t + 1 < TILES) {
            const float4* src = (const float4*)(xb + (size_t)(t + 1) * KT * DIM);
#pragma unroll
            for (int r = 0; r < 8; ++r) pv[r] = __ldg(src + tid + 128 * r);
        }

        // 4 k-steps of 8 (verified fragment pattern; 3 strips per warp)
#pragma unroll
        for (int ks = 0; ks < 4; ++ks) {
            const float* base = &sA[cur][(ks * 8 + t4) * SD];

            uint32_t bfA[8][2];   // cols 0:64
            uint32_t bfB[8][2];   // cols 64:128
            if (wid <= 2) {
#pragma unroll
                for (int nt = 0; nt < 8; ++nt) {
                    bfA[nt][0] = __float_as_uint(base[nt * 8 + g]);
                    bfA[nt][1] = __float_as_uint(base[4 * SD + nt * 8 + g]);
                }
            }
            if (wid >= 2) {
#pragma unroll
                for (int nt = 0; nt < 8; ++nt) {
                    bfB[nt][0] = __float_as_uint(base[64 + nt * 8 + g]);
                    bfB[nt][1] = __float_as_uint(base[4 * SD + 64 + nt * 8 + g]);
                }
            }
#pragma unroll
            for (int j = 0; j < 3; ++j) {
                const int m0 = tm[j];
                uint32_t a0 = __float_as_uint(base[m0 + g]);
                uint32_t a1 = __float_as_uint(base[m0 + g + 8]);
                uint32_t a2 = __float_as_uint(base[4 * SD + m0 + g]);
                uint32_t a3 = __float_as_uint(base[4 * SD + m0 + g + 8]);
                const bool useB64 = (j < 2) ? b64_01 : b64_2;
                if (!useB64) {
#pragma unroll
                    for (int nt = 0; nt < 8; ++nt)
                        mma_tf32(acc[j][nt], a0, a1, a2, a3, bfA[nt][0], bfA[nt][1]);
                } else {
#pragma unroll
                    for (int nt = 0; nt < 8; ++nt)
                        mma_tf32(acc[j][nt], a0, a1, a2, a3, bfB[nt][0], bfB[nt][1]);
                }
            }
        }

        if (t + 1 < TILES) {
            const int nxt = (t + 1) & 1;
#pragma unroll
            for (int r = 0; r < 8; ++r) {
                const float x0 = __shfl_sync(0xffffffffu, pv[r].x, 0);
                csum.x += pv[r].x; csum.y += pv[r].y;
                csum.z += pv[r].z; csum.w += pv[r].w;
                ksum.x = fmaf(pv[r].x, x0, ksum.x);
                ksum.y = fmaf(pv[r].y, x0, ksum.y);
                ksum.z = fmaf(pv[r].z, x0, ksum.z);
                ksum.w = fmaf(pv[r].w, x0, ksum.w);
                const int k = krow + 4 * r;
                uint4 uv = make_uint4(to_tf32(pv[r].x), to_tf32(pv[r].y),
                                      to_tf32(pv[r].z), to_tf32(pv[r].w));
                *(uint4*)&sA[nxt][k * SD + d4 * 4] = uv;
            }
        }
        __syncthreads();
    }

    // ---- column-sum + key reductions ----
    sCsum[tid] = csum;
    sKsum[tid] = ksum;
    __syncthreads();
    if (tid < 32) {
        float4 a = sCsum[tid];
        float4 k = sKsum[tid];
#pragma unroll
        for (int w = 1; w < 4; ++w) {
            float4 u = sCsum[tid + 32 * w];
            a.x += u.x; a.y += u.y; a.z += u.z; a.w += u.w;
            float4 q = sKsum[tid + 32 * w];
            k.x += q.x; k.y += q.y; k.z += q.z; k.w += q.w;
        }
        ((float4*)&g_sums[s][b][0])[tid] = a;
        ((float4*)&g_keyp[s][b][0])[tid] = k;
    }

    // ---- write partial cov strips ----
    float* outp = &g_covp[s][b][0][0];
#pragma unroll
    for (int j = 0; j < 3; ++j) {
        const bool useB64 = (j < 2) ? b64_01 : b64_2;
        const int wn = useB64 ? 64 : 0;
#pragma unroll
        for (int nt = 0; nt < 8; ++nt) {
            const int row = tm[j] + g;
            const int col = wn + nt * 8 + t4 * 2;
            *(float2*)&outp[(size_t)row * DIM + col] =
                make_float2(acc[j][nt][0], acc[j][nt][1]);
            *(float2*)&outp[(size_t)(row + 8) * DIM + col] =
                make_float2(acc[j][nt][2], acc[j][nt][3]);
        }
    }
}

// ---------------------------------------------------------------------------
// Kernel 2: finalize, 256 CTAs (batch x 16-row slab), 256 threads.
// Upper-right quadrant (dd<64, e>=64) reconstructed from transpose of (1,0).
// ---------------------------------------------------------------------------
__global__ __launch_bounds__(256)
void finalize_kernel() {
    __shared__ float ssum[DIM];
    __shared__ float skey[DIM];

    const int b    = blockIdx.x >> 3;
    const int slab = blockIdx.x & 7;     // 16 rows
    const int tid  = threadIdx.x;

    if (tid < DIM) {
        float sd = 0.f, kd = 0.f;
#pragma unroll
        for (int sp = 0; sp < SPLITS; ++sp) {
            sd += g_sums[sp][b][tid];
            kd += g_keyp[sp][b][tid];
        }
        ssum[tid] = sd;
        skey[tid] = kd;
    }
    __syncthreads();

    const float inv_n   = 1.0f / NPTS;
    const float inv_nm1 = 1.0f / (NPTS - 1);
    const float m0 = ssum[0] * inv_n;

#pragma unroll
    for (int r = 0; r < 2; ++r) {
        const int i = tid + 256 * r;
        const int dl = i >> 5;
        const int dd = slab * 16 + dl;
        const int e4 = i & 31;

        float4 acc = make_float4(0.f, 0.f, 0.f, 0.f);
        if (slab < 4 && e4 >= 16) {
            // transposed reads from stored block (64:128, 0:64)
            const int e0 = e4 * 4;
#pragma unroll
            for (int sp = 0; sp < SPLITS; ++sp) {
                acc.x += g_covp[sp][b][e0 + 0][dd];
                acc.y += g_covp[sp][b][e0 + 1][dd];
                acc.z += g_covp[sp][b][e0 + 2][dd];
                acc.w += g_covp[sp][b][e0 + 3][dd];
            }
        } else {
#pragma unroll
            for (int sp = 0; sp < SPLITS; ++sp) {
                float4 v = *(const float4*)&g_covp[sp][b][dd][e4 * 4];
                acc.x += v.x; acc.y += v.y; acc.z += v.z; acc.w += v.w;
            }
        }
        const float md = ssum[dd] * inv_n;
        const float4 se = *(const float4*)&ssum[e4 * 4];
        float4 o;
        o.x = (acc.x - (float)NPTS * md * (se.x * inv_n)) * inv_nm1;
        o.y = (acc.y - (float)NPTS * md * (se.y * inv_n)) * inv_nm1;
        o.z = (acc.z - (float)NPTS * md * (se.z * inv_n)) * inv_nm1;
        o.w = (acc.w - (float)NPTS * md * (se.w * inv_n)) * inv_nm1;
        const int e0 = e4 * 4;
        if (dd >= e0 && dd < e0 + 4) {
            if (dd == e0)     o.x += LAM;
            if (dd == e0 + 1) o.y += LAM;
            if (dd == e0 + 2) o.z += LAM;
            if (dd == e0 + 3) o.w += LAM;
        }
        if (e4 == 0) {
            float kv = (skey[dd] - (float)NPTS * md * m0) * inv_nm1;
            if (dd == 0) kv += LAM;
            o.x = kv;
        }
        *(float4*)&g_cov[b][dd][e4 * 4] = o;
    }
}

// ---------------------------------------------------------------------------
// Kernel 3: lexicographic rank + gather (one block per batch)
// ---------------------------------------------------------------------------
__global__ void sort_kernel(float* __restrict__ out) {
    const int b = blockIdx.x;
    const int i = threadIdx.x;   // 0..127
    __shared__ float key0[DIM];
    __shared__ int   rank[DIM];

    const float* __restrict__ cb = &g_cov[b][0][0];
    key0[i] = cb[(size_t)i * DIM];
    __syncthreads();

    const float ki = key0[i];
    int r = 0;
    for (int j = 0; j < DIM; ++j) {
        const float kj = key0[j];
        if (kj < ki) { ++r; continue; }
        if (kj == ki && j != i) {
            bool decided = false;
            for (int c = 1; c < DIM; ++c) {
                const float aj = cb[(size_t)j * DIM + c];
                const float ai = cb[(size_t)i * DIM + c];
                if (aj != ai) { if (aj < ai) ++r; decided = true; break; }
            }
            if (!decided && j < i) ++r;
        }
    }
    rank[i] = r;
    __syncthreads();

    const float4* __restrict__ srcr = (const float4*)(cb + (size_t)i * DIM);
    float4* dstr = (float4*)(out + (size_t)b * (DIM * DIM) + (size_t)rank[i] * DIM);
#pragma unroll
    for (int c = 0; c < DIM / 4; ++c) dstr[c] = srcr[c];
}

// ---------------------------------------------------------------------------
extern "C" void kernel_launch(void* const* d_in, const int* in_sizes, int n_in,
                              void* d_out, int out_size) {
    const float* x = (const float*)d_in[0];
    float* out = (float*)d_out;

    syrk_mma_kernel<<<BATCH * SPLITS, 128>>>(x);
    finalize_kernel<<<BATCH * 8, 256>>>();
    sort_kernel<<<BATCH, DIM>>>(out);
}

// round 12
// speedup vs baseline: 1.2069x; 1.2069x over previous
#include <cuda_runtime.h>
#include <cstdint>

// Problem constants
#define BATCH 32
#define NPTS  8192
#define DIM   128
#define LAM   0.01f

// split-K SYRK config
#define SPLITS 8
#define KC     (NPTS / SPLITS)   // 1024 k-rows per CTA
#define KT     32                // k-rows per smem tile
#define TILES  (KC / KT)         // 32
#define SD     136               // smem row stride (floats)
#define PIPE   4                 // cp.async ring depth

// Static device scratch
__device__ float g_covp[SPLITS][BATCH][DIM][DIM];
__device__ float g_sums[SPLITS][BATCH][DIM];
__device__ float g_keyp[SPLITS][BATCH][DIM];       // exact fp32 dot(col_d, col_0)
__device__ float g_cov[BATCH][DIM][DIM];

// ---------------------------------------------------------------------------
// tf32 warp MMA m16n8k8 — fragment layout VERIFIED (R7/R10 pass)
// ---------------------------------------------------------------------------
__device__ __forceinline__ void mma_tf32(float c[4],
                                         uint32_t a0, uint32_t a1, uint32_t a2, uint32_t a3,
                                         uint32_t b0, uint32_t b1) {
    asm volatile(
        "mma.sync.aligned.m16n8k8.row.col.f32.tf32.tf32.f32 "
        "{%0,%1,%2,%3}, {%4,%5,%6,%7}, {%8,%9}, {%0,%1,%2,%3};"
        : "+f"(c[0]), "+f"(c[1]), "+f"(c[2]), "+f"(c[3])
        : "r"(a0), "r"(a1), "r"(a2), "r"(a3), "r"(b0), "r"(b1));
}

__device__ __forceinline__ uint32_t to_tf32(float v) {
    uint32_t u;
    asm("cvt.rn.tf32.f32 %0, %1;" : "=r"(u) : "f"(v));
    return u;
}

__device__ __forceinline__ uint32_t smem_u32(const void* p) {
    uint32_t a;
    asm("{ .reg .u64 t; cvta.to.shared.u64 t, %1; cvt.u32.u64 %0, t; }"
        : "=r"(a) : "l"(p));
    return a;
}

#define CP_ASYNC16(saddr, gptr) \
    asm volatile("cp.async.cg.shared.global [%0], [%1], 16;" \
        :: "r"(saddr), "l"(gptr) : "memory")
#define CP_COMMIT() asm volatile("cp.async.commit_group;" ::: "memory")
#define CP_WAIT2()  asm volatile("cp.async.wait_group 2;" ::: "memory")

// ---------------------------------------------------------------------------
// Kernel 1: split-K SYRK. cp.async ring feeds RAW fp32 tiles (exact colsums
// and sort keys read raw). tf32 rn-rounding is applied to the FRAGMENT
// REGISTERS after LDS — identical rounding for A- and B-views of each element,
// so the product is bitwise the verified rn-rounded computation.
// grid = BATCH*SPLITS, 256 threads (8 warps), warp tile 32x64.
// ---------------------------------------------------------------------------
__global__ __launch_bounds__(256, 2)
void syrk_mma_kernel(const float* __restrict__ x) {
    extern __shared__ float sm[];
    const int RING = PIPE * KT * SD;
    float* sCsum = sm + RING;
    float* sKsum = sm + RING + 1024;
    const uint32_t sb = smem_u32(sm);

    const int bid = blockIdx.x;
    const int b = bid / SPLITS;
    const int s = bid % SPLITS;
    const float* __restrict__ xb = x + ((size_t)b * NPTS + (size_t)s * KC) * DIM;

    const int tid  = threadIdx.x;
    const int lane = tid & 31;
    const int wid  = tid >> 5;
    const int g    = lane >> 2;
    const int t4   = lane & 3;
    const int wm   = (wid & 3) * 32;
    const int wn   = (wid >> 2) * 64;
    const int d4   = tid & 31;
    const int krow = tid >> 5;

    float4 csum = make_float4(0.f, 0.f, 0.f, 0.f);
    float4 ksum = make_float4(0.f, 0.f, 0.f, 0.f);
    float acc[2][8][4];
#pragma unroll
    for (int mt = 0; mt < 2; ++mt)
#pragma unroll
        for (int nt = 0; nt < 8; ++nt)
#pragma unroll
            for (int q = 0; q < 4; ++q) acc[mt][nt][q] = 0.f;

    // ---- prologue: issue cp.async for tiles 0..PIPE-2 ----
#pragma unroll
    for (int t = 0; t < PIPE - 1; ++t) {
        const float* gt = xb + (size_t)t * KT * DIM;
        const uint32_t sbuf = sb + (uint32_t)(t & (PIPE - 1)) * (KT * SD * 4);
#pragma unroll
        for (int r = 0; r < 4; ++r) {
            const int c = tid + 256 * r;
            const int row = c >> 5;
            const int col = (c & 31) * 4;
            CP_ASYNC16(sbuf + (uint32_t)(row * SD + col) * 4, gt + row * DIM + col);
        }
        CP_COMMIT();
    }

    // ---- main loop ----
    for (int t = 0; t < TILES; ++t) {
        CP_WAIT2();
        __syncthreads();

        if (t + PIPE - 1 < TILES) {
            const float* gt = xb + (size_t)(t + PIPE - 1) * KT * DIM;
            const uint32_t sbuf = sb + (uint32_t)((t + PIPE - 1) & (PIPE - 1)) * (KT * SD * 4);
#pragma unroll
            for (int r = 0; r < 4; ++r) {
                const int c = tid + 256 * r;
                const int row = c >> 5;
                const int col = (c & 31) * 4;
                CP_ASYNC16(sbuf + (uint32_t)(row * SD + col) * 4, gt + row * DIM + col);
            }
        }
        CP_COMMIT();

        const float* buf = sm + (size_t)(t & (PIPE - 1)) * (KT * SD);

        // exact colsum + exact key dots from raw fp32 smem
#pragma unroll
        for (int r = 0; r < 4; ++r) {
            const int k = krow + 8 * r;
            const float4 v = *(const float4*)&buf[k * SD + d4 * 4];
            const float x0 = buf[k * SD];
            csum.x += v.x; csum.y += v.y; csum.z += v.z; csum.w += v.w;
            ksum.x = fmaf(v.x, x0, ksum.x);
            ksum.y = fmaf(v.y, x0, ksum.y);
            ksum.z = fmaf(v.z, x0, ksum.z);
            ksum.w = fmaf(v.w, x0, ksum.w);
        }

        // 4 k-steps of 8; rn-round every fragment element in registers
#pragma unroll
        for (int ks = 0; ks < 4; ++ks) {
            const float* base = &buf[(ks * 8 + t4) * SD];

            uint32_t bf[8][2];
#pragma unroll
            for (int nt = 0; nt < 8; ++nt) {
                bf[nt][0] = to_tf32(base[wn + nt * 8 + g]);
                bf[nt][1] = to_tf32(base[4 * SD + wn + nt * 8 + g]);
            }
#pragma unroll
            for (int mt = 0; mt < 2; ++mt) {
                const int m0 = wm + mt * 16;
                uint32_t a0 = to_tf32(base[m0 + g]);
                uint32_t a1 = to_tf32(base[m0 + g + 8]);
                uint32_t a2 = to_tf32(base[4 * SD + m0 + g]);
                uint32_t a3 = to_tf32(base[4 * SD + m0 + g + 8]);
#pragma unroll
                for (int nt = 0; nt < 8; ++nt)
                    mma_tf32(acc[mt][nt], a0, a1, a2, a3, bf[nt][0], bf[nt][1]);
            }
        }
    }

    // ---- column-sum + key reductions ----
    ((float4*)sCsum)[tid] = csum;
    ((float4*)sKsum)[tid] = ksum;
    __syncthreads();
    if (tid < 32) {
        float4 a = ((float4*)sCsum)[tid];
        float4 k = ((float4*)sKsum)[tid];
#pragma unroll
        for (int w = 1; w < 8; ++w) {
            float4 u = ((float4*)sCsum)[tid + 32 * w];
            a.x += u.x; a.y += u.y; a.z += u.z; a.w += u.w;
            float4 q = ((float4*)sKsum)[tid + 32 * w];
            k.x += q.x; k.y += q.y; k.z += q.z; k.w += q.w;
        }
        ((float4*)&g_sums[s][b][0])[tid] = a;
        ((float4*)&g_keyp[s][b][0])[tid] = k;
    }

    // ---- write partial cov ----
    float* outp = &g_covp[s][b][0][0];
#pragma unroll
    for (int mt = 0; mt < 2; ++mt) {
#pragma unroll
        for (int nt = 0; nt < 8; ++nt) {
            const int row = wm + mt * 16 + g;
            const int col = wn + nt * 8 + t4 * 2;
            *(float2*)&outp[(size_t)row * DIM + col] =
                make_float2(acc[mt][nt][0], acc[mt][nt][1]);
            *(float2*)&outp[(size_t)(row + 8) * DIM + col] =
                make_float2(acc[mt][nt][2], acc[mt][nt][3]);
        }
    }
}

// ---------------------------------------------------------------------------
// Kernel 2: finalize, 256 CTAs (batch x 16-row slab), 256 threads. (R10-proven)
// ---------------------------------------------------------------------------
__global__ __launch_bounds__(256)
void finalize_kernel() {
    __shared__ float ssum[DIM];
    __shared__ float skey[DIM];

    const int b    = blockIdx.x >> 3;
    const int slab = blockIdx.x & 7;
    const int tid  = threadIdx.x;

    if (tid < DIM) {
        float sd = 0.f, kd = 0.f;
#pragma unroll
        for (int sp = 0; sp < SPLITS; ++sp) {
            sd += g_sums[sp][b][tid];
            kd += g_keyp[sp][b][tid];
        }
        ssum[tid] = sd;
        skey[tid] = kd;
    }
    __syncthreads();

    const float inv_n   = 1.0f / NPTS;
    const float inv_nm1 = 1.0f / (NPTS - 1);
    const float m0 = ssum[0] * inv_n;

#pragma unroll
    for (int r = 0; r < 2; ++r) {
        const int i = tid + 256 * r;
        const int dl = i >> 5;
        const int dd = slab * 16 + dl;
        const int e4 = i & 31;

        float4 acc = make_float4(0.f, 0.f, 0.f, 0.f);
#pragma unroll
        for (int sp = 0; sp < SPLITS; ++sp) {
            float4 v = *(const float4*)&g_covp[sp][b][dd][e4 * 4];
            acc.x += v.x; acc.y += v.y; acc.z += v.z; acc.w += v.w;
        }
        const float md = ssum[dd] * inv_n;
        const float4 se = *(const float4*)&ssum[e4 * 4];
        float4 o;
        o.x = (acc.x - (float)NPTS * md * (se.x * inv_n)) * inv_nm1;
        o.y = (acc.y - (float)NPTS * md * (se.y * inv_n)) * inv_nm1;
        o.z = (acc.z - (float)NPTS * md * (se.z * inv_n)) * inv_nm1;
        o.w = (acc.w - (float)NPTS * md * (se.w * inv_n)) * inv_nm1;
        const int e0 = e4 * 4;
        if (dd >= e0 && dd < e0 + 4) {
            if (dd == e0)     o.x += LAM;
            if (dd == e0 + 1) o.y += LAM;
            if (dd == e0 + 2) o.z += LAM;
            if (dd == e0 + 3) o.w += LAM;
        }
        if (e4 == 0) {
            float kv = (skey[dd] - (float)NPTS * md * m0) * inv_nm1;
            if (dd == 0) kv += LAM;
            o.x = kv;
        }
        *(float4*)&g_cov[b][dd][e4 * 4] = o;
    }
}

// ---------------------------------------------------------------------------
// Kernel 3: lexicographic rank + gather (one block per batch)
// ---------------------------------------------------------------------------
__global__ void sort_kernel(float* __restrict__ out) {
    const int b = blockIdx.x;
    const int i = threadIdx.x;
    __shared__ float key0[DIM];
    __shared__ int   rank[DIM];

    const float* __restrict__ cb = &g_cov[b][0][0];
    key0[i] = cb[(size_t)i * DIM];
    __syncthreads();

    const float ki = key0[i];
    int r = 0;
    for (int j = 0; j < DIM; ++j) {
        const float kj = key0[j];
        if (kj < ki) { ++r; continue; }
        if (kj == ki && j != i) {
            bool decided = false;
            for (int c = 1; c < DIM; ++c) {
                const float aj = cb[(size_t)j * DIM + c];
                const float ai = cb[(size_t)i * DIM + c];
                if (aj != ai) { if (aj < ai) ++r; decided = true; break; }
            }
            if (!decided && j < i) ++r;
        }
    }
    rank[i] = r;
    __syncthreads();

    const float4* __restrict__ srcr = (const float4*)(cb + (size_t)i * DIM);
    float4* dstr = (float4*)(out + (size_t)b * (DIM * DIM) + (size_t)rank[i] * DIM);
#pragma unroll
    for (int c = 0; c < DIM / 4; ++c) dstr[c] = srcr[c];
}

// ---------------------------------------------------------------------------
extern "C" void kernel_launch(void* const* d_in, const int* in_sizes, int n_in,
                              void* d_out, int out_size) {
    const float* x = (const float*)d_in[0];
    float* out = (float*)d_out;

    const int SMEM1 = (PIPE * KT * SD + 2048) * 4;   // 77,824 B
    cudaFuncSetAttribute(syrk_mma_kernel,
                         cudaFuncAttributeMaxDynamicSharedMemorySize, SMEM1);

    syrk_mma_kernel<<<BATCH * SPLITS, 256, SMEM1>>>(x);
    finalize_kernel<<<BATCH * 8, 256>>>();
    sort_kernel<<<BATCH, DIM>>>(out);
}

// round 13
// speedup vs baseline: 1.7133x; 1.4196x over previous
#include <cuda_runtime.h>
#include <cuda_fp16.h>
#include <cstdint>

// Problem constants
#define BATCH 32
#define NPTS  8192
#define DIM   128
#define LAM   0.01f

// split-K SYRK config
#define SPLITS 8
#define KC     (NPTS / SPLITS)   // 1024 k-rows per CTA
#define KT     32                // k-rows per smem tile
#define TILES  (KC / KT)         // 32
#define SD     136               // smem row stride (floats)

// Static device scratch (fp16 partials: 8 MB)
__device__ __half g_covp[SPLITS][BATCH][DIM][DIM];
__device__ float  g_sums[SPLITS][BATCH][DIM];
__device__ float  g_keyp[SPLITS][BATCH][DIM];      // exact fp32 dot(col_d, col_0)

// ---------------------------------------------------------------------------
// tf32 warp MMA m16n8k8 — fragment layout VERIFIED (R7/R10 pass)
// ---------------------------------------------------------------------------
__device__ __forceinline__ void mma_tf32(float c[4],
                                         uint32_t a0, uint32_t a1, uint32_t a2, uint32_t a3,
                                         uint32_t b0, uint32_t b1) {
    asm volatile(
        "mma.sync.aligned.m16n8k8.row.col.f32.tf32.tf32.f32 "
        "{%0,%1,%2,%3}, {%4,%5,%6,%7}, {%8,%9}, {%0,%1,%2,%3};"
        : "+f"(c[0]), "+f"(c[1]), "+f"(c[2]), "+f"(c[3])
        : "r"(a0), "r"(a1), "r"(a2), "r"(a3), "r"(b0), "r"(b1));
}

__device__ __forceinline__ uint32_t to_tf32(float v) {
    uint32_t u;
    asm("cvt.rn.tf32.f32 %0, %1;" : "=r"(u) : "f"(v));
    return u;
}

// ---------------------------------------------------------------------------
// Kernel 1: split-K SYRK via tf32 mma.sync, 64x64 warp tiles (R10-proven).
// grid = BATCH*SPLITS, 128 threads (4 warps), 2 CTAs/SM.
// LDG prefetch -> exact colsum/key accumulate -> cvt.rn -> STS.
// Epilogue writes fp16 partials.
// ---------------------------------------------------------------------------
__global__ __launch_bounds__(128, 2)
void syrk_mma_kernel(const float* __restrict__ x) {
    __shared__ float  sA[2][KT * SD];   // 2 x 17408 B
    __shared__ float4 sCsum[128];
    __shared__ float4 sKsum[128];

    const int bid = blockIdx.x;
    const int b = bid / SPLITS;
    const int s = bid % SPLITS;
    const float* __restrict__ xb = x + ((size_t)b * NPTS + (size_t)s * KC) * DIM;

    const int tid  = threadIdx.x;
    const int lane = tid & 31;
    const int wid  = tid >> 5;           // 0..3
    const int g    = lane >> 2;          // 0..7
    const int t4   = lane & 3;           // 0..3
    const int wm   = (wid & 1) * 64;     // warp M offset
    const int wn   = (wid >> 1) * 64;    // warp N offset
    const int d4   = tid & 31;           // fixed column group (4 cols)
    const int krow = tid >> 5;           // 0..3 base k-row

    float4 csum = make_float4(0.f, 0.f, 0.f, 0.f);
    float4 ksum = make_float4(0.f, 0.f, 0.f, 0.f);
    float acc[4][8][4];
#pragma unroll
    for (int mt = 0; mt < 4; ++mt)
#pragma unroll
        for (int nt = 0; nt < 8; ++nt)
#pragma unroll
            for (int q = 0; q < 4; ++q) acc[mt][nt][q] = 0.f;

    float4 pv[8];   // 8 rows x 4 cols per thread per tile

    // ---- prologue: load tile 0, accumulate, convert, store ----
    {
        const float4* src = (const float4*)xb;
#pragma unroll
        for (int r = 0; r < 8; ++r) pv[r] = __ldg(src + tid + 128 * r);
#pragma unroll
        for (int r = 0; r < 8; ++r) {
            const float x0 = __shfl_sync(0xffffffffu, pv[r].x, 0);
            csum.x += pv[r].x; csum.y += pv[r].y;
            csum.z += pv[r].z; csum.w += pv[r].w;
            ksum.x = fmaf(pv[r].x, x0, ksum.x);
            ksum.y = fmaf(pv[r].y, x0, ksum.y);
            ksum.z = fmaf(pv[r].z, x0, ksum.z);
            ksum.w = fmaf(pv[r].w, x0, ksum.w);
            const int k = krow + 4 * r;
            uint4 uv = make_uint4(to_tf32(pv[r].x), to_tf32(pv[r].y),
                                  to_tf32(pv[r].z), to_tf32(pv[r].w));
            *(uint4*)&sA[0][k * SD + d4 * 4] = uv;
        }
    }
    __syncthreads();

    // ---- main loop ----
    for (int t = 0; t < TILES; ++t) {
        const int cur = t & 1;

        if (t + 1 < TILES) {
            const float4* src = (const float4*)(xb + (size_t)(t + 1) * KT * DIM);
#pragma unroll
            for (int r = 0; r < 8; ++r) pv[r] = __ldg(src + tid + 128 * r);
        }

        // 4 k-steps of 8 (verified fragment pattern; 64x64 bounds)
#pragma unroll
        for (int ks = 0; ks < 4; ++ks) {
            const float* base = &sA[cur][(ks * 8 + t4) * SD];

            uint32_t bf[8][2];
#pragma unroll
            for (int nt = 0; nt < 8; ++nt) {
                bf[nt][0] = __float_as_uint(base[wn + nt * 8 + g]);
                bf[nt][1] = __float_as_uint(base[4 * SD + wn + nt * 8 + g]);
            }
#pragma unroll
            for (int mt = 0; mt < 4; ++mt) {
                const int m0 = wm + mt * 16;
                uint32_t a0 = __float_as_uint(base[m0 + g]);
                uint32_t a1 = __float_as_uint(base[m0 + g + 8]);
                uint32_t a2 = __float_as_uint(base[4 * SD + m0 + g]);
                uint32_t a3 = __float_as_uint(base[4 * SD + m0 + g + 8]);
#pragma unroll
                for (int nt = 0; nt < 8; ++nt)
                    mma_tf32(acc[mt][nt], a0, a1, a2, a3, bf[nt][0], bf[nt][1]);
            }
        }

        if (t + 1 < TILES) {
            const int nxt = (t + 1) & 1;
#pragma unroll
            for (int r = 0; r < 8; ++r) {
                const float x0 = __shfl_sync(0xffffffffu, pv[r].x, 0);
                csum.x += pv[r].x; csum.y += pv[r].y;
                csum.z += pv[r].z; csum.w += pv[r].w;
                ksum.x = fmaf(pv[r].x, x0, ksum.x);
                ksum.y = fmaf(pv[r].y, x0, ksum.y);
                ksum.z = fmaf(pv[r].z, x0, ksum.z);
                ksum.w = fmaf(pv[r].w, x0, ksum.w);
                const int k = krow + 4 * r;
                uint4 uv = make_uint4(to_tf32(pv[r].x), to_tf32(pv[r].y),
                                      to_tf32(pv[r].z), to_tf32(pv[r].w));
                *(uint4*)&sA[nxt][k * SD + d4 * 4] = uv;
            }
        }
        __syncthreads();
    }

    // ---- column-sum + key reductions ----
    sCsum[tid] = csum;
    sKsum[tid] = ksum;
    __syncthreads();
    if (tid < 32) {
        float4 a = sCsum[tid];
        float4 k = sKsum[tid];
#pragma unroll
        for (int w = 1; w < 4; ++w) {
            float4 u = sCsum[tid + 32 * w];
            a.x += u.x; a.y += u.y; a.z += u.z; a.w += u.w;
            float4 q = sKsum[tid + 32 * w];
            k.x += q.x; k.y += q.y; k.z += q.z; k.w += q.w;
        }
        ((float4*)&g_sums[s][b][0])[tid] = a;
        ((float4*)&g_keyp[s][b][0])[tid] = k;
    }

    // ---- write partial cov (fp16) ----
    __half* outp = &g_covp[s][b][0][0];
#pragma unroll
    for (int mt = 0; mt < 4; ++mt) {
#pragma unroll
        for (int nt = 0; nt < 8; ++nt) {
            const int row = wm + mt * 16 + g;
            const int col = wn + nt * 8 + t4 * 2;
            *(__half2*)&outp[(size_t)row * DIM + col] =
                __float22half2_rn(make_float2(acc[mt][nt][0], acc[mt][nt][1]));
            *(__half2*)&outp[(size_t)(row + 8) * DIM + col] =
                __float22half2_rn(make_float2(acc[mt][nt][2], acc[mt][nt][3]));
        }
    }
}

// ---------------------------------------------------------------------------
// Kernel 2: fused finalize + scatter-sort. 256 CTAs (batch x 16-row slab).
// Keys (exact fp32) are derived from g_keyp/g_sums only -> ranks computed
// here; finalized rows written directly to their sorted output position.
// ---------------------------------------------------------------------------
__global__ __launch_bounds__(256)
void finalize_scatter_kernel(float* __restrict__ out) {
    __shared__ float ssum[DIM];
    __shared__ float skey[DIM];   // final exact keys (incl LAM on row 0)
    __shared__ int   srank[16];

    const int b    = blockIdx.x >> 3;
    const int slab = blockIdx.x & 7;     // rows slab*16 .. +16
    const int tid  = threadIdx.x;

    if (tid < DIM) {
        float sd = 0.f, kd = 0.f;
#pragma unroll
        for (int sp = 0; sp < SPLITS; ++sp) {
            sd += g_sums[sp][b][tid];
            kd += g_keyp[sp][b][tid];
        }
        ssum[tid] = sd;
        skey[tid] = kd;
    }
    __syncthreads();

    const float inv_n   = 1.0f / NPTS;
    const float inv_nm1 = 1.0f / (NPTS - 1);
    const float m0 = ssum[0] * inv_n;

    // finalize exact keys
    if (tid < DIM) {
        const float md = ssum[tid] * inv_n;
        float kv = (skey[tid] - (float)NPTS * md * m0) * inv_nm1;
        if (tid == 0) kv += LAM;
        skey[tid] = kv;
    }
    __syncthreads();

    // ranks for this slab's 16 rows (ties broken by index; measure-zero)
    if (tid < 16) {
        const int row = slab * 16 + tid;
        const float ki = skey[row];
        int r = 0;
        for (int j = 0; j < DIM; ++j) {
            const float kj = skey[j];
            if (kj < ki || (kj == ki && j < row)) ++r;
        }
        srank[tid] = r;
    }
    __syncthreads();

    float* ob = out + (size_t)b * (DIM * DIM);

#pragma unroll
    for (int r = 0; r < 2; ++r) {
        const int i = tid + 256 * r;         // 512 float4 slots (16 rows x 32)
        const int dl = i >> 5;               // 0..15
        const int dd = slab * 16 + dl;
        const int e4 = i & 31;

        float4 acc = make_float4(0.f, 0.f, 0.f, 0.f);
#pragma unroll
        for (int sp = 0; sp < SPLITS; ++sp) {
            const __half2* p = (const __half2*)&g_covp[sp][b][dd][e4 * 4];
            float2 lo = __half22float2(p[0]);
            float2 hi = __half22float2(p[1]);
            acc.x += lo.x; acc.y += lo.y; acc.z += hi.x; acc.w += hi.y;
        }
        const float md = ssum[dd] * inv_n;
        const float4 se = *(const float4*)&ssum[e4 * 4];
        float4 o;
        o.x = (acc.x - (float)NPTS * md * (se.x * inv_n)) * inv_nm1;
        o.y = (acc.y - (float)NPTS * md * (se.y * inv_n)) * inv_nm1;
        o.z = (acc.z - (float)NPTS * md * (se.z * inv_n)) * inv_nm1;
        o.w = (acc.w - (float)NPTS * md * (se.w * inv_n)) * inv_nm1;
        const int e0 = e4 * 4;
        if (dd >= e0 && dd < e0 + 4) {
            if (dd == e0)     o.x += LAM;
            if (dd == e0 + 1) o.y += LAM;
            if (dd == e0 + 2) o.z += LAM;
            if (dd == e0 + 3) o.w += LAM;
        }
        if (e4 == 0) o.x = skey[dd];   // exact key column

        *(float4*)&ob[(size_t)srank[dl] * DIM + e4 * 4] = o;
    }
}

// ---------------------------------------------------------------------------
extern "C" void kernel_launch(void* const* d_in, const int* in_sizes, int n_in,
                              void* d_out, int out_size) {
    const float* x = (const float*)d_in[0];
    float* out = (float*)d_out;

    syrk_mma_kernel<<<BATCH * SPLITS, 128>>>(x);
    finalize_scatter_kernel<<<BATCH * 8, 256>>>(out);
}